// round 7
// baseline (speedup 1.0000x reference)
#include <cuda_runtime.h>
#include <cuda_bf16.h>
#include <math_constants.h>

#define E  512
#define L  1024
#define B2 512
#define CHUNK 128

__device__ float g_v[E];
__device__ float g_c;
__device__ float g_scores[B2 * L];     // raw attention energies
__device__ float g_partial[128 * E];   // prep stage-A partials

// ---------------------------------------------------------------------------
// Prep stage A: 128 blocks x 512 threads. Block j reduces W rows [4j, 4j+4);
// thread t owns column e = t (scalar, coalesced).
// ---------------------------------------------------------------------------
__global__ __launch_bounds__(512)
void prep_partial(const float* __restrict__ W,
                  const float* __restrict__ wv) {
    const int j = blockIdx.x;           // 0..127
    const int e = threadIdx.x;          // 0..511
    const int f0 = j * 4;

    float acc = 0.f;
    #pragma unroll
    for (int r = 0; r < 4; ++r)
        acc = fmaf(__ldg(W + (size_t)(f0 + r) * E + e), __ldg(wv + f0 + r), acc);
    g_partial[(size_t)j * E + e] = acc;
}

// ---------------------------------------------------------------------------
// Prep stage B: fold 128 partials into g_v; block 0 computes c = bias . wv.
// ---------------------------------------------------------------------------
__global__ __launch_bounds__(128)
void prep_reduce(const float* __restrict__ bias,
                 const float* __restrict__ wv) {
    __shared__ float s_red[4];
    const int t = threadIdx.x;
    const int e = blockIdx.x * 128 + t;

    float s = 0.f;
    #pragma unroll 16
    for (int j = 0; j < 128; ++j)
        s += g_partial[j * E + e];
    g_v[e] = s;

    if (blockIdx.x == 0) {
        const int warp = t >> 5, lane = t & 31;
        float part = 0.f;
        #pragma unroll
        for (int f = t; f < E; f += 128)
            part = fmaf(__ldg(bias + f), __ldg(wv + f), part);
        #pragma unroll
        for (int o = 16; o; o >>= 1)
            part += __shfl_down_sync(0xffffffffu, part, o);
        if (lane == 0) s_red[warp] = part;
        __syncthreads();
        if (t == 0)
            g_c = s_red[0] + s_red[1] + s_red[2] + s_red[3];
    }
}

// ---------------------------------------------------------------------------
// Scores: grid (L/CHUNK, B2), 256 threads = 8 warps, 16 tokens per warp.
// R2-proven inner loop — DO NOT modify (R3/R6 unroll variants both regressed).
// ---------------------------------------------------------------------------
__global__ __launch_bounds__(256)
void scores_kernel(const float* __restrict__ q,
                   const int* __restrict__ lens) {
    __shared__ float s_v[E];

    const int tid  = threadIdx.x;
    const int warp = tid >> 5;
    const int lane = tid & 31;
    const int b    = blockIdx.y;
    const int base = blockIdx.x * CHUNK;
    const int len  = lens[b];

    if (base >= len) return;                 // whole chunk masked out

    #pragma unroll
    for (int i = tid; i < E; i += 256) s_v[i] = g_v[i];
    __syncthreads();

    const float c = g_c;
    const float4* __restrict__ vv = reinterpret_cast<const float4*>(s_v);
    const float*  __restrict__ qrow = q + (size_t)b * L * E;
    const int tok_end = min(base + CHUNK, len);

    for (int l = base + warp * 16; l < min(base + warp * 16 + 16, tok_end); ++l) {
        const float4* __restrict__ qp =
            reinterpret_cast<const float4*>(qrow + (size_t)l * E);
        float acc = 0.f;
        #pragma unroll
        for (int k = 0; k < 4; ++k) {
            float4 a = __ldg(qp + k * 32 + lane);
            float4 w = vv[k * 32 + lane];
            acc = fmaf(a.x, w.x, acc);
            acc = fmaf(a.y, w.y, acc);
            acc = fmaf(a.z, w.z, acc);
            acc = fmaf(a.w, w.w, acc);
        }
        #pragma unroll
        for (int o = 16; o; o >>= 1)
            acc += __shfl_down_sync(0xffffffffu, acc, o);
        if (lane == 0) g_scores[b * L + l] = acc + c;
    }
}

// ---------------------------------------------------------------------------
// Softmax over valid prefix. One block of 256 per row; float4 I/O,
// 4 elements per thread, two compact reduce stages.
// ---------------------------------------------------------------------------
__global__ __launch_bounds__(256)
void softmax_kernel(const int* __restrict__ lens,
                    float* __restrict__ out) {
    __shared__ float s_red[8];
    __shared__ float s_bcast;

    const int tid  = threadIdx.x;
    const int warp = tid >> 5;
    const int lane = tid & 31;
    const int b    = blockIdx.x;
    const int len  = lens[b];
    const int i0   = tid * 4;

    float4 sc = *reinterpret_cast<const float4*>(g_scores + b * L + i0);
    float x0 = (i0 + 0 < len) ? sc.x : -CUDART_INF_F;
    float x1 = (i0 + 1 < len) ? sc.y : -CUDART_INF_F;
    float x2 = (i0 + 2 < len) ? sc.z : -CUDART_INF_F;
    float x3 = (i0 + 3 < len) ? sc.w : -CUDART_INF_F;

    float m = fmaxf(fmaxf(x0, x1), fmaxf(x2, x3));
    #pragma unroll
    for (int o = 16; o; o >>= 1)
        m = fmaxf(m, __shfl_down_sync(0xffffffffu, m, o));
    if (lane == 0) s_red[warp] = m;
    __syncthreads();
    if (warp == 0) {
        float t = (lane < 8) ? s_red[lane] : -CUDART_INF_F;
        #pragma unroll
        for (int o = 4; o; o >>= 1)
            t = fmaxf(t, __shfl_down_sync(0xffffffffu, t, o));
        if (lane == 0) s_bcast = t;
    }
    __syncthreads();
    const float rowmax = s_bcast;

    float e0 = (i0 + 0 < len) ? __expf(x0 - rowmax) : 0.f;
    float e1 = (i0 + 1 < len) ? __expf(x1 - rowmax) : 0.f;
    float e2 = (i0 + 2 < len) ? __expf(x2 - rowmax) : 0.f;
    float e3 = (i0 + 3 < len) ? __expf(x3 - rowmax) : 0.f;

    float s = e0 + e1 + e2 + e3;
    #pragma unroll
    for (int o = 16; o; o >>= 1)
        s += __shfl_down_sync(0xffffffffu, s, o);
    __syncthreads();
    if (lane == 0) s_red[warp] = s;
    __syncthreads();
    if (warp == 0) {
        float t = (lane < 8) ? s_red[lane] : 0.f;
        #pragma unroll
        for (int o = 4; o; o >>= 1)
            t += __shfl_down_sync(0xffffffffu, t, o);
        if (lane == 0) s_bcast = t;
    }
    __syncthreads();
    const float inv = 1.f / s_bcast;

    float4 r = make_float4(e0 * inv, e1 * inv, e2 * inv, e3 * inv);
    *reinterpret_cast<float4*>(out + (size_t)b * L + i0) = r;
}

extern "C" void kernel_launch(void* const* d_in, const int* in_sizes, int n_in,
                              void* d_out, int out_size) {
    const float* questions = (const float*)d_in[0];   // [B2, L, E]
    const int*   lens      = (const int*)d_in[1];     // [B2]
    const float* W         = (const float*)d_in[2];   // [E, E]
    const float* bias      = (const float*)d_in[3];   // [E]
    const float* wv        = (const float*)d_in[4];   // [E, 1]
    float* out             = (float*)d_out;           // [B2, L]

    prep_partial<<<128, 512>>>(W, wv);
    prep_reduce<<<4, 128>>>(bias, wv);
    dim3 sgrid(L / CHUNK, B2);
    scores_kernel<<<sgrid, 256>>>(questions, lens);
    softmax_kernel<<<B2, 256>>>(lens, out);
}

// round 8
// speedup vs baseline: 1.0040x; 1.0040x over previous
#include <cuda_runtime.h>
#include <cuda_bf16.h>
#include <math_constants.h>

#define E  512
#define L  1024
#define B2 512
#define CHUNK 128

__device__ float g_v[E];
__device__ float g_c;
__device__ float g_scores[B2 * L];     // raw attention energies
__device__ float g_partial[128 * E];   // prep stage-A partials
__device__ unsigned int g_pctr;        // prep arrival counter (self-resetting)

// ---------------------------------------------------------------------------
// Fused prep: 128 blocks x 512 threads. Block j reduces W rows [4j,4j+4)
// into g_partial; the last block to arrive folds partials into g_v and
// computes c = bias . wv. Counter self-resets (last block zeroes it).
// ---------------------------------------------------------------------------
__global__ __launch_bounds__(512)
void prep_kernel(const float* __restrict__ W,
                 const float* __restrict__ bias,
                 const float* __restrict__ wv) {
    __shared__ int s_last;
    const int j = blockIdx.x;           // 0..127
    const int t = threadIdx.x;          // 0..511
    const int f0 = j * 4;

    float acc = 0.f;
    #pragma unroll
    for (int r = 0; r < 4; ++r)
        acc = fmaf(__ldg(W + (size_t)(f0 + r) * E + t), __ldg(wv + f0 + r), acc);
    g_partial[(size_t)j * E + t] = acc;

    __threadfence();
    __syncthreads();
    if (t == 0)
        s_last = (atomicAdd(&g_pctr, 1u) == 127u);
    __syncthreads();
    if (!s_last) return;
    __threadfence();

    // fold 128 partials into g_v[t]
    float s = 0.f;
    #pragma unroll 16
    for (int k = 0; k < 128; ++k)
        s += g_partial[k * E + t];
    g_v[t] = s;

    // c = bias . wv (warp 0 finishes it)
    __shared__ float s_red[16];
    const int warp = t >> 5, lane = t & 31;
    float part = __ldg(bias + t) * __ldg(wv + t);
    #pragma unroll
    for (int o = 16; o; o >>= 1)
        part += __shfl_down_sync(0xffffffffu, part, o);
    if (lane == 0) s_red[warp] = part;
    __syncthreads();
    if (warp == 0) {
        float v = (lane < 16) ? s_red[lane] : 0.f;
        #pragma unroll
        for (int o = 8; o; o >>= 1)
            v += __shfl_down_sync(0xffffffffu, v, o);
        if (lane == 0) g_c = v;
    }
    if (t == 0) g_pctr = 0;             // reset for next graph replay
}

// ---------------------------------------------------------------------------
// Scores: grid (L/CHUNK, B2), 256 threads = 8 warps, 16 tokens per warp.
// R2-proven inner loop — DO NOT modify. PDL: prelude before gridsync.
// ---------------------------------------------------------------------------
__global__ __launch_bounds__(256)
void scores_kernel(const float* __restrict__ q,
                   const int* __restrict__ lens) {
    __shared__ float s_v[E];

    const int tid  = threadIdx.x;
    const int warp = tid >> 5;
    const int lane = tid & 31;
    const int b    = blockIdx.y;
    const int base = blockIdx.x * CHUNK;
    const int len  = lens[b];            // input, independent of prep

    cudaGridDependencySynchronize();     // wait for g_v / g_c

    if (base >= len) return;             // whole chunk masked out

    #pragma unroll
    for (int i = tid; i < E; i += 256) s_v[i] = g_v[i];
    __syncthreads();

    const float c = g_c;
    const float4* __restrict__ vv = reinterpret_cast<const float4*>(s_v);
    const float*  __restrict__ qrow = q + (size_t)b * L * E;
    const int tok_end = min(base + CHUNK, len);

    for (int l = base + warp * 16; l < min(base + warp * 16 + 16, tok_end); ++l) {
        const float4* __restrict__ qp =
            reinterpret_cast<const float4*>(qrow + (size_t)l * E);
        float acc = 0.f;
        #pragma unroll
        for (int k = 0; k < 4; ++k) {
            float4 a = __ldg(qp + k * 32 + lane);
            float4 w = vv[k * 32 + lane];
            acc = fmaf(a.x, w.x, acc);
            acc = fmaf(a.y, w.y, acc);
            acc = fmaf(a.z, w.z, acc);
            acc = fmaf(a.w, w.w, acc);
        }
        #pragma unroll
        for (int o = 16; o; o >>= 1)
            acc += __shfl_down_sync(0xffffffffu, acc, o);
        if (lane == 0) g_scores[b * L + l] = acc + c;
    }
}

// ---------------------------------------------------------------------------
// Softmax over valid prefix. One 256-thread block per row, float4 I/O.
// PDL: prelude (lens) before gridsync.
// ---------------------------------------------------------------------------
__global__ __launch_bounds__(256)
void softmax_kernel(const int* __restrict__ lens,
                    float* __restrict__ out) {
    __shared__ float s_red[8];
    __shared__ float s_bcast;

    const int tid  = threadIdx.x;
    const int warp = tid >> 5;
    const int lane = tid & 31;
    const int b    = blockIdx.x;
    const int len  = lens[b];            // input, independent of scores
    const int i0   = tid * 4;

    cudaGridDependencySynchronize();     // wait for g_scores

    float4 sc = *reinterpret_cast<const float4*>(g_scores + b * L + i0);
    float x0 = (i0 + 0 < len) ? sc.x : -CUDART_INF_F;
    float x1 = (i0 + 1 < len) ? sc.y : -CUDART_INF_F;
    float x2 = (i0 + 2 < len) ? sc.z : -CUDART_INF_F;
    float x3 = (i0 + 3 < len) ? sc.w : -CUDART_INF_F;

    float m = fmaxf(fmaxf(x0, x1), fmaxf(x2, x3));
    #pragma unroll
    for (int o = 16; o; o >>= 1)
        m = fmaxf(m, __shfl_down_sync(0xffffffffu, m, o));
    if (lane == 0) s_red[warp] = m;
    __syncthreads();
    if (warp == 0) {
        float t = (lane < 8) ? s_red[lane] : -CUDART_INF_F;
        #pragma unroll
        for (int o = 4; o; o >>= 1)
            t = fmaxf(t, __shfl_down_sync(0xffffffffu, t, o));
        if (lane == 0) s_bcast = t;
    }
    __syncthreads();
    const float rowmax = s_bcast;

    float e0 = (i0 + 0 < len) ? __expf(x0 - rowmax) : 0.f;
    float e1 = (i0 + 1 < len) ? __expf(x1 - rowmax) : 0.f;
    float e2 = (i0 + 2 < len) ? __expf(x2 - rowmax) : 0.f;
    float e3 = (i0 + 3 < len) ? __expf(x3 - rowmax) : 0.f;

    float s = e0 + e1 + e2 + e3;
    #pragma unroll
    for (int o = 16; o; o >>= 1)
        s += __shfl_down_sync(0xffffffffu, s, o);
    __syncthreads();
    if (lane == 0) s_red[warp] = s;
    __syncthreads();
    if (warp == 0) {
        float t = (lane < 8) ? s_red[lane] : 0.f;
        #pragma unroll
        for (int o = 4; o; o >>= 1)
            t += __shfl_down_sync(0xffffffffu, t, o);
        if (lane == 0) s_bcast = t;
    }
    __syncthreads();
    const float inv = 1.f / s_bcast;

    float4 r = make_float4(e0 * inv, e1 * inv, e2 * inv, e3 * inv);
    *reinterpret_cast<float4*>(out + (size_t)b * L + i0) = r;
}

extern "C" void kernel_launch(void* const* d_in, const int* in_sizes, int n_in,
                              void* d_out, int out_size) {
    const float* questions = (const float*)d_in[0];   // [B2, L, E]
    const int*   lens      = (const int*)d_in[1];     // [B2]
    const float* W         = (const float*)d_in[2];   // [E, E]
    const float* bias      = (const float*)d_in[3];   // [E]
    const float* wv        = (const float*)d_in[4];   // [E, 1]
    float* out             = (float*)d_out;           // [B2, L]

    prep_kernel<<<128, 512>>>(W, bias, wv);

    cudaLaunchAttribute attr[1];
    attr[0].id = cudaLaunchAttributeProgrammaticStreamSerialization;
    attr[0].val.programmaticStreamSerializationAllowed = 1;

    {   // scores with PDL
        cudaLaunchConfig_t cfg = {};
        cfg.gridDim  = dim3(L / CHUNK, B2);
        cfg.blockDim = dim3(256);
        cfg.stream   = 0;
        cfg.attrs    = attr;
        cfg.numAttrs = 1;
        cudaLaunchKernelEx(&cfg, scores_kernel, questions, lens);
    }
    {   // softmax with PDL
        cudaLaunchConfig_t cfg = {};
        cfg.gridDim  = dim3(B2);
        cfg.blockDim = dim3(256);
        cfg.stream   = 0;
        cfg.attrs    = attr;
        cfg.numAttrs = 1;
        cudaLaunchKernelEx(&cfg, softmax_kernel, lens, out);
    }
}

// round 9
// speedup vs baseline: 1.0189x; 1.0148x over previous
#include <cuda_runtime.h>
#include <cuda_bf16.h>
#include <math_constants.h>

#define E  512
#define L  1024
#define B2 512
#define CHUNK 128

__device__ float g_v[E];
__device__ float g_c;
__device__ float g_scores[B2 * L];     // raw attention energies
__device__ float g_partial[128 * E];   // prep stage-A partials

// ---------------------------------------------------------------------------
// Prep stage A: 128 blocks x 512 threads. Block j reduces W rows [4j, 4j+4);
// thread t owns column e = t (scalar, coalesced). No fences, no atomics.
// ---------------------------------------------------------------------------
__global__ __launch_bounds__(512)
void prep_partial(const float* __restrict__ W,
                  const float* __restrict__ wv) {
    const int j = blockIdx.x;           // 0..127
    const int e = threadIdx.x;          // 0..511
    const int f0 = j * 4;

    float acc = 0.f;
    #pragma unroll
    for (int r = 0; r < 4; ++r)
        acc = fmaf(__ldg(W + (size_t)(f0 + r) * E + e), __ldg(wv + f0 + r), acc);
    g_partial[(size_t)j * E + e] = acc;
}

// ---------------------------------------------------------------------------
// Prep stage B: fold 128 partials into g_v; block 0 computes c = bias . wv.
// PDL: bias/wv prelude before gridsync.
// ---------------------------------------------------------------------------
__global__ __launch_bounds__(128)
void prep_reduce(const float* __restrict__ bias,
                 const float* __restrict__ wv) {
    __shared__ float s_red[4];
    const int t = threadIdx.x;
    const int e = blockIdx.x * 128 + t;
    const int warp = t >> 5, lane = t & 31;

    // prelude: c partial from inputs (independent of prep_partial)
    float part = 0.f;
    if (blockIdx.x == 0) {
        #pragma unroll
        for (int f = t; f < E; f += 128)
            part = fmaf(__ldg(bias + f), __ldg(wv + f), part);
    }

    cudaGridDependencySynchronize();    // wait for g_partial

    float s = 0.f;
    #pragma unroll 16
    for (int j = 0; j < 128; ++j)
        s += g_partial[j * E + e];
    g_v[e] = s;

    if (blockIdx.x == 0) {
        #pragma unroll
        for (int o = 16; o; o >>= 1)
            part += __shfl_down_sync(0xffffffffu, part, o);
        if (lane == 0) s_red[warp] = part;
        __syncthreads();
        if (t == 0)
            g_c = s_red[0] + s_red[1] + s_red[2] + s_red[3];
    }
}

// ---------------------------------------------------------------------------
// Scores: grid (L/CHUNK, B2), 256 threads = 8 warps, 16 tokens per warp.
// R2-proven inner loop — DO NOT modify. PDL: lens prelude before gridsync.
// ---------------------------------------------------------------------------
__global__ __launch_bounds__(256)
void scores_kernel(const float* __restrict__ q,
                   const int* __restrict__ lens) {
    __shared__ float s_v[E];

    const int tid  = threadIdx.x;
    const int warp = tid >> 5;
    const int lane = tid & 31;
    const int b    = blockIdx.y;
    const int base = blockIdx.x * CHUNK;
    const int len  = lens[b];            // input, independent of prep

    cudaGridDependencySynchronize();     // wait for g_v / g_c

    if (base >= len) return;             // whole chunk masked out

    #pragma unroll
    for (int i = tid; i < E; i += 256) s_v[i] = g_v[i];
    __syncthreads();

    const float c = g_c;
    const float4* __restrict__ vv = reinterpret_cast<const float4*>(s_v);
    const float*  __restrict__ qrow = q + (size_t)b * L * E;
    const int tok_end = min(base + CHUNK, len);

    for (int l = base + warp * 16; l < min(base + warp * 16 + 16, tok_end); ++l) {
        const float4* __restrict__ qp =
            reinterpret_cast<const float4*>(qrow + (size_t)l * E);
        float acc = 0.f;
        #pragma unroll
        for (int k = 0; k < 4; ++k) {
            float4 a = __ldg(qp + k * 32 + lane);
            float4 w = vv[k * 32 + lane];
            acc = fmaf(a.x, w.x, acc);
            acc = fmaf(a.y, w.y, acc);
            acc = fmaf(a.z, w.z, acc);
            acc = fmaf(a.w, w.w, acc);
        }
        #pragma unroll
        for (int o = 16; o; o >>= 1)
            acc += __shfl_down_sync(0xffffffffu, acc, o);
        if (lane == 0) g_scores[b * L + l] = acc + c;
    }
}

// ---------------------------------------------------------------------------
// Softmax over valid prefix. One 256-thread block per row, float4 I/O.
// PDL: lens prelude before gridsync.
// ---------------------------------------------------------------------------
__global__ __launch_bounds__(256)
void softmax_kernel(const int* __restrict__ lens,
                    float* __restrict__ out) {
    __shared__ float s_red[8];
    __shared__ float s_bcast;

    const int tid  = threadIdx.x;
    const int warp = tid >> 5;
    const int lane = tid & 31;
    const int b    = blockIdx.x;
    const int len  = lens[b];            // input, independent of scores
    const int i0   = tid * 4;

    cudaGridDependencySynchronize();     // wait for g_scores

    float4 sc = *reinterpret_cast<const float4*>(g_scores + b * L + i0);
    float x0 = (i0 + 0 < len) ? sc.x : -CUDART_INF_F;
    float x1 = (i0 + 1 < len) ? sc.y : -CUDART_INF_F;
    float x2 = (i0 + 2 < len) ? sc.z : -CUDART_INF_F;
    float x3 = (i0 + 3 < len) ? sc.w : -CUDART_INF_F;

    float m = fmaxf(fmaxf(x0, x1), fmaxf(x2, x3));
    #pragma unroll
    for (int o = 16; o; o >>= 1)
        m = fmaxf(m, __shfl_down_sync(0xffffffffu, m, o));
    if (lane == 0) s_red[warp] = m;
    __syncthreads();
    if (warp == 0) {
        float t = (lane < 8) ? s_red[lane] : -CUDART_INF_F;
        #pragma unroll
        for (int o = 4; o; o >>= 1)
            t = fmaxf(t, __shfl_down_sync(0xffffffffu, t, o));
        if (lane == 0) s_bcast = t;
    }
    __syncthreads();
    const float rowmax = s_bcast;

    float e0 = (i0 + 0 < len) ? __expf(x0 - rowmax) : 0.f;
    float e1 = (i0 + 1 < len) ? __expf(x1 - rowmax) : 0.f;
    float e2 = (i0 + 2 < len) ? __expf(x2 - rowmax) : 0.f;
    float e3 = (i0 + 3 < len) ? __expf(x3 - rowmax) : 0.f;

    float s = e0 + e1 + e2 + e3;
    #pragma unroll
    for (int o = 16; o; o >>= 1)
        s += __shfl_down_sync(0xffffffffu, s, o);
    __syncthreads();
    if (lane == 0) s_red[warp] = s;
    __syncthreads();
    if (warp == 0) {
        float t = (lane < 8) ? s_red[lane] : 0.f;
        #pragma unroll
        for (int o = 4; o; o >>= 1)
            t += __shfl_down_sync(0xffffffffu, t, o);
        if (lane == 0) s_bcast = t;
    }
    __syncthreads();
    const float inv = 1.f / s_bcast;

    float4 r = make_float4(e0 * inv, e1 * inv, e2 * inv, e3 * inv);
    *reinterpret_cast<float4*>(out + (size_t)b * L + i0) = r;
}

extern "C" void kernel_launch(void* const* d_in, const int* in_sizes, int n_in,
                              void* d_out, int out_size) {
    const float* questions = (const float*)d_in[0];   // [B2, L, E]
    const int*   lens      = (const int*)d_in[1];     // [B2]
    const float* W         = (const float*)d_in[2];   // [E, E]
    const float* bias      = (const float*)d_in[3];   // [E]
    const float* wv        = (const float*)d_in[4];   // [E, 1]
    float* out             = (float*)d_out;           // [B2, L]

    prep_partial<<<128, 512>>>(W, wv);

    cudaLaunchAttribute attr[1];
    attr[0].id = cudaLaunchAttributeProgrammaticStreamSerialization;
    attr[0].val.programmaticStreamSerializationAllowed = 1;

    {   // prep_reduce with PDL
        cudaLaunchConfig_t cfg = {};
        cfg.gridDim  = dim3(4);
        cfg.blockDim = dim3(128);
        cfg.stream   = 0;
        cfg.attrs    = attr;
        cfg.numAttrs = 1;
        cudaLaunchKernelEx(&cfg, prep_reduce, bias, wv);
    }
    {   // scores with PDL
        cudaLaunchConfig_t cfg = {};
        cfg.gridDim  = dim3(L / CHUNK, B2);
        cfg.blockDim = dim3(256);
        cfg.stream   = 0;
        cfg.attrs    = attr;
        cfg.numAttrs = 1;
        cudaLaunchKernelEx(&cfg, scores_kernel, questions, lens);
    }
    {   // softmax with PDL
        cudaLaunchConfig_t cfg = {};
        cfg.gridDim  = dim3(B2);
        cfg.blockDim = dim3(256);
        cfg.stream   = 0;
        cfg.attrs    = attr;
        cfg.numAttrs = 1;
        cudaLaunchKernelEx(&cfg, softmax_kernel, lens, out);
    }
}

// round 10
// speedup vs baseline: 1.0413x; 1.0220x over previous
#include <cuda_runtime.h>
#include <cuda_bf16.h>
#include <math_constants.h>

#define E  512
#define L  1024
#define B2 512
#define CHUNK 128
#define NPART 16     // prep partial count (blocks); scores folds these

__device__ float g_c;
__device__ float g_scores[B2 * L];       // raw attention energies
__device__ float g_partial[NPART * E];   // prep partials (folded by scores)

// ---------------------------------------------------------------------------
// Prep: 16 blocks x 512 threads. Block j reduces W rows [32j, 32j+32) into
// g_partial[j]; block 0 also computes c = bias . wv (single-block, exact).
// ---------------------------------------------------------------------------
__global__ __launch_bounds__(512)
void prep_kernel(const float* __restrict__ W,
                 const float* __restrict__ bias,
                 const float* __restrict__ wv) {
    __shared__ float s_wv[32];
    __shared__ float s_red[16];
    const int j = blockIdx.x;           // 0..NPART-1
    const int t = threadIdx.x;          // 0..511 (column e)
    const int f0 = j * 32;

    if (t < 32) s_wv[t] = __ldg(wv + f0 + t);
    __syncthreads();

    float acc = 0.f;
    #pragma unroll
    for (int r = 0; r < 32; ++r)
        acc = fmaf(__ldg(W + (size_t)(f0 + r) * E + t), s_wv[r], acc);
    g_partial[(size_t)j * E + t] = acc;

    if (j == 0) {
        const int warp = t >> 5, lane = t & 31;
        float part = __ldg(bias + t) * __ldg(wv + t);
        #pragma unroll
        for (int o = 16; o; o >>= 1)
            part += __shfl_down_sync(0xffffffffu, part, o);
        if (lane == 0) s_red[warp] = part;
        __syncthreads();
        if (warp == 0) {
            float v = (lane < 16) ? s_red[lane] : 0.f;
            #pragma unroll
            for (int o = 8; o; o >>= 1)
                v += __shfl_down_sync(0xffffffffu, v, o);
            if (lane == 0) g_c = v;
        }
    }
}

// ---------------------------------------------------------------------------
// Scores: grid (L/CHUNK, B2), 256 threads = 8 warps, 16 tokens per warp.
// Folds the NPART prep partials while staging s_v (L2-resident, hidden).
// R2-proven inner loop — DO NOT modify. PDL: lens prelude before gridsync.
// ---------------------------------------------------------------------------
__global__ __launch_bounds__(256)
void scores_kernel(const float* __restrict__ q,
                   const int* __restrict__ lens) {
    __shared__ float s_v[E];

    const int tid  = threadIdx.x;
    const int warp = tid >> 5;
    const int lane = tid & 31;
    const int b    = blockIdx.y;
    const int base = blockIdx.x * CHUNK;
    const int len  = lens[b];            // input, independent of prep

    cudaGridDependencySynchronize();     // wait for g_partial / g_c

    if (base >= len) return;             // whole chunk masked out

    #pragma unroll
    for (int i = tid; i < E; i += 256) {
        float s = 0.f;
        #pragma unroll
        for (int jj = 0; jj < NPART; ++jj)
            s += g_partial[jj * E + i];
        s_v[i] = s;
    }
    __syncthreads();

    const float c = g_c;
    const float4* __restrict__ vv = reinterpret_cast<const float4*>(s_v);
    const float*  __restrict__ qrow = q + (size_t)b * L * E;
    const int tok_end = min(base + CHUNK, len);

    for (int l = base + warp * 16; l < min(base + warp * 16 + 16, tok_end); ++l) {
        const float4* __restrict__ qp =
            reinterpret_cast<const float4*>(qrow + (size_t)l * E);
        float acc = 0.f;
        #pragma unroll
        for (int k = 0; k < 4; ++k) {
            float4 a = __ldg(qp + k * 32 + lane);
            float4 w = vv[k * 32 + lane];
            acc = fmaf(a.x, w.x, acc);
            acc = fmaf(a.y, w.y, acc);
            acc = fmaf(a.z, w.z, acc);
            acc = fmaf(a.w, w.w, acc);
        }
        #pragma unroll
        for (int o = 16; o; o >>= 1)
            acc += __shfl_down_sync(0xffffffffu, acc, o);
        if (lane == 0) g_scores[b * L + l] = acc + c;
    }
}

// ---------------------------------------------------------------------------
// Softmax over valid prefix. One 256-thread block per row, float4 I/O.
// PDL: lens prelude before gridsync.
// ---------------------------------------------------------------------------
__global__ __launch_bounds__(256)
void softmax_kernel(const int* __restrict__ lens,
                    float* __restrict__ out) {
    __shared__ float s_red[8];
    __shared__ float s_bcast;

    const int tid  = threadIdx.x;
    const int warp = tid >> 5;
    const int lane = tid & 31;
    const int b    = blockIdx.x;
    const int len  = lens[b];            // input, independent of scores
    const int i0   = tid * 4;

    cudaGridDependencySynchronize();     // wait for g_scores

    float4 sc = *reinterpret_cast<const float4*>(g_scores + b * L + i0);
    float x0 = (i0 + 0 < len) ? sc.x : -CUDART_INF_F;
    float x1 = (i0 + 1 < len) ? sc.y : -CUDART_INF_F;
    float x2 = (i0 + 2 < len) ? sc.z : -CUDART_INF_F;
    float x3 = (i0 + 3 < len) ? sc.w : -CUDART_INF_F;

    float m = fmaxf(fmaxf(x0, x1), fmaxf(x2, x3));
    #pragma unroll
    for (int o = 16; o; o >>= 1)
        m = fmaxf(m, __shfl_down_sync(0xffffffffu, m, o));
    if (lane == 0) s_red[warp] = m;
    __syncthreads();
    if (warp == 0) {
        float t = (lane < 8) ? s_red[lane] : -CUDART_INF_F;
        #pragma unroll
        for (int o = 4; o; o >>= 1)
            t = fmaxf(t, __shfl_down_sync(0xffffffffu, t, o));
        if (lane == 0) s_bcast = t;
    }
    __syncthreads();
    const float rowmax = s_bcast;

    float e0 = (i0 + 0 < len) ? __expf(x0 - rowmax) : 0.f;
    float e1 = (i0 + 1 < len) ? __expf(x1 - rowmax) : 0.f;
    float e2 = (i0 + 2 < len) ? __expf(x2 - rowmax) : 0.f;
    float e3 = (i0 + 3 < len) ? __expf(x3 - rowmax) : 0.f;

    float s = e0 + e1 + e2 + e3;
    #pragma unroll
    for (int o = 16; o; o >>= 1)
        s += __shfl_down_sync(0xffffffffu, s, o);
    __syncthreads();
    if (lane == 0) s_red[warp] = s;
    __syncthreads();
    if (warp == 0) {
        float t = (lane < 8) ? s_red[lane] : 0.f;
        #pragma unroll
        for (int o = 4; o; o >>= 1)
            t += __shfl_down_sync(0xffffffffu, t, o);
        if (lane == 0) s_bcast = t;
    }
    __syncthreads();
    const float inv = 1.f / s_bcast;

    float4 r = make_float4(e0 * inv, e1 * inv, e2 * inv, e3 * inv);
    *reinterpret_cast<float4*>(out + (size_t)b * L + i0) = r;
}

extern "C" void kernel_launch(void* const* d_in, const int* in_sizes, int n_in,
                              void* d_out, int out_size) {
    const float* questions = (const float*)d_in[0];   // [B2, L, E]
    const int*   lens      = (const int*)d_in[1];     // [B2]
    const float* W         = (const float*)d_in[2];   // [E, E]
    const float* bias      = (const float*)d_in[3];   // [E]
    const float* wv        = (const float*)d_in[4];   // [E, 1]
    float* out             = (float*)d_out;           // [B2, L]

    prep_kernel<<<NPART, 512>>>(W, bias, wv);

    cudaLaunchAttribute attr[1];
    attr[0].id = cudaLaunchAttributeProgrammaticStreamSerialization;
    attr[0].val.programmaticStreamSerializationAllowed = 1;

    {   // scores with PDL
        cudaLaunchConfig_t cfg = {};
        cfg.gridDim  = dim3(L / CHUNK, B2);
        cfg.blockDim = dim3(256);
        cfg.stream   = 0;
        cfg.attrs    = attr;
        cfg.numAttrs = 1;
        cudaLaunchKernelEx(&cfg, scores_kernel, questions, lens);
    }
    {   // softmax with PDL
        cudaLaunchConfig_t cfg = {};
        cfg.gridDim  = dim3(B2);
        cfg.blockDim = dim3(256);
        cfg.stream   = 0;
        cfg.attrs    = attr;
        cfg.numAttrs = 1;
        cudaLaunchKernelEx(&cfg, softmax_kernel, lens, out);
    }
}

// round 11
// speedup vs baseline: 1.0493x; 1.0076x over previous
#include <cuda_runtime.h>
#include <cuda_bf16.h>
#include <math_constants.h>

#define E  512
#define L  1024
#define B2 512
#define CHUNK 128
#define NPART 16     // row-group partial count; scores folds these

__device__ float g_c;
__device__ float g_scores[B2 * L];       // raw attention energies
__device__ float g_partial[NPART * E];   // prep partials (folded by scores)

// ---------------------------------------------------------------------------
// Prep: grid (4 col-groups, 16 row-groups) x 128 threads.
// Block (cg, j) reduces W rows [32j, 32j+32) over columns [128cg, 128cg+128)
// into g_partial[j][e]. Block (0,0) also computes c = bias . wv.
// ---------------------------------------------------------------------------
__global__ __launch_bounds__(128)
void prep_kernel(const float* __restrict__ W,
                 const float* __restrict__ bias,
                 const float* __restrict__ wv) {
    __shared__ float s_wv[32];
    __shared__ float s_red[4];
    const int cg = blockIdx.x;          // 0..3
    const int j  = blockIdx.y;          // 0..NPART-1
    const int t  = threadIdx.x;         // 0..127
    const int e  = cg * 128 + t;
    const int f0 = j * 32;

    if (t < 32) s_wv[t] = __ldg(wv + f0 + t);
    __syncthreads();

    float acc = 0.f;
    #pragma unroll
    for (int r = 0; r < 32; ++r)
        acc = fmaf(__ldg(W + (size_t)(f0 + r) * E + e), s_wv[r], acc);
    g_partial[(size_t)j * E + e] = acc;

    if (cg == 0 && j == 0) {
        const int warp = t >> 5, lane = t & 31;
        float part = 0.f;
        #pragma unroll
        for (int f = t; f < E; f += 128)
            part = fmaf(__ldg(bias + f), __ldg(wv + f), part);
        #pragma unroll
        for (int o = 16; o; o >>= 1)
            part += __shfl_down_sync(0xffffffffu, part, o);
        if (lane == 0) s_red[warp] = part;
        __syncthreads();
        if (t == 0)
            g_c = s_red[0] + s_red[1] + s_red[2] + s_red[3];
    }
}

// ---------------------------------------------------------------------------
// Scores: grid (L/CHUNK, B2), 256 threads = 8 warps, 16 tokens per warp.
// Folds the NPART prep partials while staging s_v (L2-resident, hidden).
// R2-proven inner loop — DO NOT modify. PDL: lens prelude before gridsync.
// ---------------------------------------------------------------------------
__global__ __launch_bounds__(256)
void scores_kernel(const float* __restrict__ q,
                   const int* __restrict__ lens) {
    __shared__ float s_v[E];

    const int tid  = threadIdx.x;
    const int warp = tid >> 5;
    const int lane = tid & 31;
    const int b    = blockIdx.y;
    const int base = blockIdx.x * CHUNK;
    const int len  = lens[b];            // input, independent of prep

    cudaGridDependencySynchronize();     // wait for g_partial / g_c

    if (base >= len) return;             // whole chunk masked out

    #pragma unroll
    for (int i = tid; i < E; i += 256) {
        float s = 0.f;
        #pragma unroll
        for (int jj = 0; jj < NPART; ++jj)
            s += g_partial[jj * E + i];
        s_v[i] = s;
    }
    __syncthreads();

    const float c = g_c;
    const float4* __restrict__ vv = reinterpret_cast<const float4*>(s_v);
    const float*  __restrict__ qrow = q + (size_t)b * L * E;
    const int tok_end = min(base + CHUNK, len);

    for (int l = base + warp * 16; l < min(base + warp * 16 + 16, tok_end); ++l) {
        const float4* __restrict__ qp =
            reinterpret_cast<const float4*>(qrow + (size_t)l * E);
        float acc = 0.f;
        #pragma unroll
        for (int k = 0; k < 4; ++k) {
            float4 a = __ldg(qp + k * 32 + lane);
            float4 w = vv[k * 32 + lane];
            acc = fmaf(a.x, w.x, acc);
            acc = fmaf(a.y, w.y, acc);
            acc = fmaf(a.z, w.z, acc);
            acc = fmaf(a.w, w.w, acc);
        }
        #pragma unroll
        for (int o = 16; o; o >>= 1)
            acc += __shfl_down_sync(0xffffffffu, acc, o);
        if (lane == 0) g_scores[b * L + l] = acc + c;
    }
}

// ---------------------------------------------------------------------------
// Softmax over valid prefix. One 256-thread block per row, float4 I/O.
// PDL: lens prelude before gridsync.
// ---------------------------------------------------------------------------
__global__ __launch_bounds__(256)
void softmax_kernel(const int* __restrict__ lens,
                    float* __restrict__ out) {
    __shared__ float s_red[8];
    __shared__ float s_bcast;

    const int tid  = threadIdx.x;
    const int warp = tid >> 5;
    const int lane = tid & 31;
    const int b    = blockIdx.x;
    const int len  = lens[b];            // input, independent of scores
    const int i0   = tid * 4;

    cudaGridDependencySynchronize();     // wait for g_scores

    float4 sc = *reinterpret_cast<const float4*>(g_scores + b * L + i0);
    float x0 = (i0 + 0 < len) ? sc.x : -CUDART_INF_F;
    float x1 = (i0 + 1 < len) ? sc.y : -CUDART_INF_F;
    float x2 = (i0 + 2 < len) ? sc.z : -CUDART_INF_F;
    float x3 = (i0 + 3 < len) ? sc.w : -CUDART_INF_F;

    float m = fmaxf(fmaxf(x0, x1), fmaxf(x2, x3));
    #pragma unroll
    for (int o = 16; o; o >>= 1)
        m = fmaxf(m, __shfl_down_sync(0xffffffffu, m, o));
    if (lane == 0) s_red[warp] = m;
    __syncthreads();
    if (warp == 0) {
        float t = (lane < 8) ? s_red[lane] : -CUDART_INF_F;
        #pragma unroll
        for (int o = 4; o; o >>= 1)
            t = fmaxf(t, __shfl_down_sync(0xffffffffu, t, o));
        if (lane == 0) s_bcast = t;
    }
    __syncthreads();
    const float rowmax = s_bcast;

    float e0 = (i0 + 0 < len) ? __expf(x0 - rowmax) : 0.f;
    float e1 = (i0 + 1 < len) ? __expf(x1 - rowmax) : 0.f;
    float e2 = (i0 + 2 < len) ? __expf(x2 - rowmax) : 0.f;
    float e3 = (i0 + 3 < len) ? __expf(x3 - rowmax) : 0.f;

    float s = e0 + e1 + e2 + e3;
    #pragma unroll
    for (int o = 16; o; o >>= 1)
        s += __shfl_down_sync(0xffffffffu, s, o);
    __syncthreads();
    if (lane == 0) s_red[warp] = s;
    __syncthreads();
    if (warp == 0) {
        float t = (lane < 8) ? s_red[lane] : 0.f;
        #pragma unroll
        for (int o = 4; o; o >>= 1)
            t += __shfl_down_sync(0xffffffffu, t, o);
        if (lane == 0) s_bcast = t;
    }
    __syncthreads();
    const float inv = 1.f / s_bcast;

    float4 r = make_float4(e0 * inv, e1 * inv, e2 * inv, e3 * inv);
    *reinterpret_cast<float4*>(out + (size_t)b * L + i0) = r;
}

extern "C" void kernel_launch(void* const* d_in, const int* in_sizes, int n_in,
                              void* d_out, int out_size) {
    const float* questions = (const float*)d_in[0];   // [B2, L, E]
    const int*   lens      = (const int*)d_in[1];     // [B2]
    const float* W         = (const float*)d_in[2];   // [E, E]
    const float* bias      = (const float*)d_in[3];   // [E]
    const float* wv        = (const float*)d_in[4];   // [E, 1]
    float* out             = (float*)d_out;           // [B2, L]

    prep_kernel<<<dim3(4, NPART), 128>>>(W, bias, wv);

    cudaLaunchAttribute attr[1];
    attr[0].id = cudaLaunchAttributeProgrammaticStreamSerialization;
    attr[0].val.programmaticStreamSerializationAllowed = 1;

    {   // scores with PDL
        cudaLaunchConfig_t cfg = {};
        cfg.gridDim  = dim3(L / CHUNK, B2);
        cfg.blockDim = dim3(256);
        cfg.stream   = 0;
        cfg.attrs    = attr;
        cfg.numAttrs = 1;
        cudaLaunchKernelEx(&cfg, scores_kernel, questions, lens);
    }
    {   // softmax with PDL
        cudaLaunchConfig_t cfg = {};
        cfg.gridDim  = dim3(B2);
        cfg.blockDim = dim3(256);
        cfg.stream   = 0;
        cfg.attrs    = attr;
        cfg.numAttrs = 1;
        cudaLaunchKernelEx(&cfg, softmax_kernel, lens, out);
    }
}